// round 1
// baseline (speedup 1.0000x reference)
#include <cuda_runtime.h>
#include <cstdint>
#include <cstddef>

#define B_ 8
#define N_ 4096
#define M_ 4096
#define C_ 256

// Scratch (no allocations allowed): reciprocal norms and the per-batch kv matrix.
__device__ float g_rq[B_ * N_];          // 1/(N*max(||q_row||,eps))
__device__ float g_rk[B_ * M_];          // 1/max(||k_row||,eps)
__device__ float g_kv[B_ * C_ * C_];     // kv[b][c][d]

__device__ __forceinline__ uint32_t f2tf(float x) {
    uint32_t r;
    asm("cvt.rna.tf32.f32 %0, %1;" : "=r"(r) : "f"(x));
    return r;
}

__device__ __forceinline__ void mma8(float c[4], const uint32_t a[4], const uint32_t b[2]) {
    asm volatile(
        "mma.sync.aligned.m16n8k8.row.col.f32.tf32.tf32.f32 "
        "{%0,%1,%2,%3}, {%4,%5,%6,%7}, {%8,%9}, {%0,%1,%2,%3};\n"
        : "+f"(c[0]), "+f"(c[1]), "+f"(c[2]), "+f"(c[3])
        : "r"(a[0]), "r"(a[1]), "r"(a[2]), "r"(a[3]),
          "r"(b[0]), "r"(b[1]));
}

// ---------------------------------------------------------------------------
// Kernel 1: reciprocal L2 norms, warp per row (C=256 => 8 floats/lane).
// ---------------------------------------------------------------------------
__global__ __launch_bounds__(256) void norm_kernel(const float* __restrict__ q,
                                                   const float* __restrict__ k) {
    int gw = (blockIdx.x * blockDim.x + threadIdx.x) >> 5;
    int lane = threadIdx.x & 31;
    const float* src;
    float* dst;
    float post;
    int idx;
    if (gw < B_ * N_) {
        idx = gw;
        src = q + (size_t)idx * C_;
        dst = g_rq;
        post = 1.0f / (float)N_;           // fold the final /N into q's scale
    } else {
        idx = gw - B_ * N_;
        src = k + (size_t)idx * C_;
        dst = g_rk;
        post = 1.0f;
    }
    float4 a = *(const float4*)(src + lane * 4);
    float4 b = *(const float4*)(src + 128 + lane * 4);
    float ss = a.x * a.x + a.y * a.y + a.z * a.z + a.w * a.w
             + b.x * b.x + b.y * b.y + b.z * b.z + b.w * b.w;
#pragma unroll
    for (int o = 16; o > 0; o >>= 1) ss += __shfl_xor_sync(0xffffffffu, ss, o);
    if (lane == 0) dst[idx] = post / fmaxf(sqrtf(ss), 1e-12f);
}

// ---------------------------------------------------------------------------
// Kernel 2: kv[b][c][d] = sum_m (k[b][m][c]*rk[b][m]) * v[b][m][d]
// tf32 MMA, CTA tile 64(c) x 64(d), BK=32 over m, K=4096.
// SMEM tiles stored k-major [32][72] (pad 72 => conflict-free STS + frag LDS).
// ---------------------------------------------------------------------------
__global__ __launch_bounds__(256) void kv_kernel(const float* __restrict__ k,
                                                 const float* __restrict__ v) {
    __shared__ uint32_t As[32 * 72];   // [m_local][c_local]
    __shared__ uint32_t Bs[32 * 72];   // [m_local][d_local]

    const int b  = blockIdx.z;
    const int c0 = blockIdx.y * 64;
    const int d0 = blockIdx.x * 64;
    const int t    = threadIdx.x;
    const int lane = t & 31;
    const int wid  = t >> 5;
    const int g    = lane >> 2;
    const int tig  = lane & 3;
    const int wc = (wid >> 2) * 32;   // warp c-offset (2 warps)
    const int wd = (wid & 3) * 16;    // warp d-offset (4 warps)

    // tile loader mapping: float4 per (row, 16-col group), rows r0 and r0+16
    const int lcol = (t & 15) * 4;
    const int lr0  = t >> 4;

    const float* kb  = k + (size_t)b * M_ * C_ + c0 + lcol;
    const float* vb  = v + (size_t)b * M_ * C_ + d0 + lcol;
    const float* rkb = g_rk + b * M_;

    float acc[2][2][4] = {};

    float4 pa[2], pb[2];
    float  ps[2];
#pragma unroll
    for (int i = 0; i < 2; i++) {
        int m = lr0 + i * 16;
        pa[i] = *(const float4*)(kb + (size_t)m * C_);
        pb[i] = *(const float4*)(vb + (size_t)m * C_);
        ps[i] = __ldg(rkb + m);
    }
#pragma unroll
    for (int i = 0; i < 2; i++) {
        int rr = lr0 + i * 16;
        float s = ps[i];
        uint32_t* ap = &As[rr * 72 + lcol];
        ap[0] = f2tf(pa[i].x * s); ap[1] = f2tf(pa[i].y * s);
        ap[2] = f2tf(pa[i].z * s); ap[3] = f2tf(pa[i].w * s);
        uint32_t* bp = &Bs[rr * 72 + lcol];
        bp[0] = f2tf(pb[i].x); bp[1] = f2tf(pb[i].y);
        bp[2] = f2tf(pb[i].z); bp[3] = f2tf(pb[i].w);
    }
    __syncthreads();

    const int KI = M_ / 32;   // 128
#pragma unroll 1
    for (int km = 0; km < KI; km++) {
        if (km + 1 < KI) {
            int mb = (km + 1) * 32;
#pragma unroll
            for (int i = 0; i < 2; i++) {
                int m = mb + lr0 + i * 16;
                pa[i] = *(const float4*)(kb + (size_t)m * C_);
                pb[i] = *(const float4*)(vb + (size_t)m * C_);
                ps[i] = __ldg(rkb + m);
            }
        }
#pragma unroll
        for (int kk = 0; kk < 4; kk++) {
            const int k8 = kk * 8;
            uint32_t afr[2][4];
            uint32_t bfr[2][2];
#pragma unroll
            for (int mt = 0; mt < 2; mt++) {
                int row = wc + mt * 16 + g;
                afr[mt][0] = As[(k8 + tig) * 72 + row];
                afr[mt][1] = As[(k8 + tig) * 72 + row + 8];
                afr[mt][2] = As[(k8 + tig + 4) * 72 + row];
                afr[mt][3] = As[(k8 + tig + 4) * 72 + row + 8];
            }
#pragma unroll
            for (int nt = 0; nt < 2; nt++) {
                int cc = wd + nt * 8 + g;
                bfr[nt][0] = Bs[(k8 + tig) * 72 + cc];
                bfr[nt][1] = Bs[(k8 + tig + 4) * 72 + cc];
            }
#pragma unroll
            for (int mt = 0; mt < 2; mt++)
#pragma unroll
                for (int nt = 0; nt < 2; nt++)
                    mma8(acc[mt][nt], afr[mt], bfr[nt]);
        }
        if (km + 1 < KI) {
            __syncthreads();
#pragma unroll
            for (int i = 0; i < 2; i++) {
                int rr = lr0 + i * 16;
                float s = ps[i];
                uint32_t* ap = &As[rr * 72 + lcol];
                ap[0] = f2tf(pa[i].x * s); ap[1] = f2tf(pa[i].y * s);
                ap[2] = f2tf(pa[i].z * s); ap[3] = f2tf(pa[i].w * s);
                uint32_t* bp = &Bs[rr * 72 + lcol];
                bp[0] = f2tf(pb[i].x); bp[1] = f2tf(pb[i].y);
                bp[2] = f2tf(pb[i].z); bp[3] = f2tf(pb[i].w);
            }
            __syncthreads();
        }
    }

#pragma unroll
    for (int mt = 0; mt < 2; mt++)
#pragma unroll
        for (int nt = 0; nt < 2; nt++) {
            int r  = c0 + wc + mt * 16 + g;
            int dd = d0 + wd + nt * 8 + tig * 2;
            float* o = g_kv + ((size_t)b * C_ + r) * C_ + dd;
            o[0]          = acc[mt][nt][0];
            o[1]          = acc[mt][nt][1];
            o[8 * C_]     = acc[mt][nt][2];
            o[8 * C_ + 1] = acc[mt][nt][3];
        }
}

// ---------------------------------------------------------------------------
// Kernel 3: out[b][n][d] = sum_c (q[b][n][c]*rq[b][n]) * kv[b][c][d]
// CTA tile 64(n) x 64(d), BK=32 over c, K=256.
// A transposed into SMEM [c][n] with pad 73 (odd stride => conflict-free).
// ---------------------------------------------------------------------------
__global__ __launch_bounds__(256) void ctx_kernel(const float* __restrict__ q,
                                                  float* __restrict__ out) {
    __shared__ uint32_t As[32 * 73];   // [c_local][n_local]
    __shared__ uint32_t Bs[32 * 72];   // [c_local][d_local]

    const int b  = blockIdx.z;
    const int n0 = blockIdx.y * 64;
    const int d0 = blockIdx.x * 64;
    const int t    = threadIdx.x;
    const int lane = t & 31;
    const int wid  = t >> 5;
    const int g    = lane >> 2;
    const int tig  = lane & 3;
    const int wn = (wid >> 2) * 32;
    const int wd = (wid & 3) * 16;

    // A loader: float4 of 4 consecutive c, rows ar0 and ar0+32
    const int ac4 = (t & 7) * 4;   // 0..28
    const int ar0 = t >> 3;        // 0..31
    const float* qb  = q + ((size_t)b * N_ + n0) * C_ + ac4;
    const float* rqb = g_rq + b * N_ + n0;
    // B loader
    const int bcol = (t & 15) * 4;
    const int br0  = t >> 4;
    const float* kvb = g_kv + (size_t)b * C_ * C_ + d0 + bcol;

    float acc[2][2][4] = {};

    float sA[2];
#pragma unroll
    for (int i = 0; i < 2; i++) sA[i] = __ldg(rqb + ar0 + i * 32);

    float4 pa[2], pb[2];
#pragma unroll
    for (int i = 0; i < 2; i++) {
        pa[i] = *(const float4*)(qb + (size_t)(ar0 + i * 32) * C_);
        pb[i] = *(const float4*)(kvb + (size_t)(br0 + i * 16) * C_);
    }
#pragma unroll
    for (int i = 0; i < 2; i++) {
        int n = ar0 + i * 32;
        float s = sA[i];
        As[(ac4 + 0) * 73 + n] = f2tf(pa[i].x * s);
        As[(ac4 + 1) * 73 + n] = f2tf(pa[i].y * s);
        As[(ac4 + 2) * 73 + n] = f2tf(pa[i].z * s);
        As[(ac4 + 3) * 73 + n] = f2tf(pa[i].w * s);
        uint32_t* bp = &Bs[(br0 + i * 16) * 72 + bcol];
        bp[0] = f2tf(pb[i].x); bp[1] = f2tf(pb[i].y);
        bp[2] = f2tf(pb[i].z); bp[3] = f2tf(pb[i].w);
    }
    __syncthreads();

    const int KI = C_ / 32;   // 8
#pragma unroll 1
    for (int ck = 0; ck < KI; ck++) {
        if (ck + 1 < KI) {
            int cb = (ck + 1) * 32;
#pragma unroll
            for (int i = 0; i < 2; i++) {
                pa[i] = *(const float4*)(qb + (size_t)(ar0 + i * 32) * C_ + cb);
                pb[i] = *(const float4*)(kvb + (size_t)(cb + br0 + i * 16) * C_);
            }
        }
#pragma unroll
        for (int kk = 0; kk < 4; kk++) {
            const int k8 = kk * 8;
            uint32_t afr[2][4];
            uint32_t bfr[2][2];
#pragma unroll
            for (int mt = 0; mt < 2; mt++) {
                int row = wn + mt * 16 + g;
                afr[mt][0] = As[(k8 + tig) * 73 + row];
                afr[mt][1] = As[(k8 + tig) * 73 + row + 8];
                afr[mt][2] = As[(k8 + tig + 4) * 73 + row];
                afr[mt][3] = As[(k8 + tig + 4) * 73 + row + 8];
            }
#pragma unroll
            for (int nt = 0; nt < 2; nt++) {
                int cc = wd + nt * 8 + g;
                bfr[nt][0] = Bs[(k8 + tig) * 72 + cc];
                bfr[nt][1] = Bs[(k8 + tig + 4) * 72 + cc];
            }
#pragma unroll
            for (int mt = 0; mt < 2; mt++)
#pragma unroll
                for (int nt = 0; nt < 2; nt++)
                    mma8(acc[mt][nt], afr[mt], bfr[nt]);
        }
        if (ck + 1 < KI) {
            __syncthreads();
#pragma unroll
            for (int i = 0; i < 2; i++) {
                int n = ar0 + i * 32;
                float s = sA[i];
                As[(ac4 + 0) * 73 + n] = f2tf(pa[i].x * s);
                As[(ac4 + 1) * 73 + n] = f2tf(pa[i].y * s);
                As[(ac4 + 2) * 73 + n] = f2tf(pa[i].z * s);
                As[(ac4 + 3) * 73 + n] = f2tf(pa[i].w * s);
                uint32_t* bp = &Bs[(br0 + i * 16) * 72 + bcol];
                bp[0] = f2tf(pb[i].x); bp[1] = f2tf(pb[i].y);
                bp[2] = f2tf(pb[i].z); bp[3] = f2tf(pb[i].w);
            }
            __syncthreads();
        }
    }

#pragma unroll
    for (int mt = 0; mt < 2; mt++)
#pragma unroll
        for (int nt = 0; nt < 2; nt++) {
            int n  = n0 + wn + mt * 16 + g;
            int dd = d0 + wd + nt * 8 + tig * 2;
            float* o = out + ((size_t)b * N_ + n) * C_ + dd;
            o[0]          = acc[mt][nt][0];
            o[1]          = acc[mt][nt][1];
            o[8 * C_]     = acc[mt][nt][2];
            o[8 * C_ + 1] = acc[mt][nt][3];
        }
}

// ---------------------------------------------------------------------------
extern "C" void kernel_launch(void* const* d_in, const int* in_sizes, int n_in,
                              void* d_out, int out_size) {
    const float* q = (const float*)d_in[0];
    const float* k = (const float*)d_in[1];
    const float* v = (const float*)d_in[2];
    float* out = (float*)d_out;

    // 1) reciprocal norms for q (with 1/N folded) and k
    norm_kernel<<<(B_ * N_ + B_ * M_) / 8, 256>>>(q, k);
    // 2) kv = k_norm^T @ v   (per batch, 256x256, K=4096)
    kv_kernel<<<dim3(4, 4, B_), 256>>>(k, v);
    // 3) out = q_norm @ kv   (per batch, 4096x256, K=256)
    ctx_kernel<<<dim3(4, 64, B_), 256>>>(q, out);
}

// round 2
// speedup vs baseline: 2.0149x; 2.0149x over previous
#include <cuda_runtime.h>
#include <cstdint>
#include <cstddef>

#define B_ 8
#define N_ 4096
#define M_ 4096
#define C_ 256

#define SPLITS 8
#define KM_PER_SPLIT 16      // 16 * 32 = 512 m-rows per split

#define STA 136              // stride (words) for [32][128] k-major tiles  (136 mod 32 = 8)
#define STQ 36               // stride (words) for [128][32] n-major q tile (36 mod 32 = 4)

// Scratch (static device arrays; no allocations allowed)
__device__ float g_rq[B_ * N_];                    // 1/(N*max(||q||,eps))
__device__ float g_rk[B_ * M_];                    // 1/max(||k||,eps)
__device__ float g_kv[B_ * C_ * C_];               // reduced kv
__device__ float g_kvp[SPLITS * B_ * C_ * C_];     // split-K partials (16 MB)

__device__ __forceinline__ uint32_t f2tf(float x) {
    uint32_t r;
    asm("cvt.rna.tf32.f32 %0, %1;" : "=r"(r) : "f"(x));
    return r;
}

__device__ __forceinline__ void mma8(float c[4], const uint32_t a[4], const uint32_t b[2]) {
    asm volatile(
        "mma.sync.aligned.m16n8k8.row.col.f32.tf32.tf32.f32 "
        "{%0,%1,%2,%3}, {%4,%5,%6,%7}, {%8,%9}, {%0,%1,%2,%3};\n"
        : "+f"(c[0]), "+f"(c[1]), "+f"(c[2]), "+f"(c[3])
        : "r"(a[0]), "r"(a[1]), "r"(a[2]), "r"(a[3]),
          "r"(b[0]), "r"(b[1]));
}

__device__ __forceinline__ void cp16(float* smem, const float* gmem) {
    uint32_t s = (uint32_t)__cvta_generic_to_shared(smem);
    asm volatile("cp.async.cg.shared.global [%0], [%1], 16;\n" :: "r"(s), "l"(gmem));
}
__device__ __forceinline__ void cp_commit() { asm volatile("cp.async.commit_group;\n" ::: "memory"); }
template <int NN>
__device__ __forceinline__ void cp_wait() { asm volatile("cp.async.wait_group %0;\n" :: "n"(NN) : "memory"); }

// ---------------------------------------------------------------------------
// Kernel 1: reciprocal L2 norms, warp per row (C=256 => 8 floats/lane).
// ---------------------------------------------------------------------------
__global__ __launch_bounds__(256) void norm_kernel(const float* __restrict__ q,
                                                   const float* __restrict__ k) {
    int gw = (blockIdx.x * blockDim.x + threadIdx.x) >> 5;
    int lane = threadIdx.x & 31;
    const float* src;
    float* dst;
    float post;
    int idx;
    if (gw < B_ * N_) {
        idx = gw;
        src = q + (size_t)idx * C_;
        dst = g_rq;
        post = 1.0f / (float)N_;
    } else {
        idx = gw - B_ * N_;
        src = k + (size_t)idx * C_;
        dst = g_rk;
        post = 1.0f;
    }
    float4 a = *(const float4*)(src + lane * 4);
    float4 b = *(const float4*)(src + 128 + lane * 4);
    float ss = a.x * a.x + a.y * a.y + a.z * a.z + a.w * a.w
             + b.x * b.x + b.y * b.y + b.z * b.z + b.w * b.w;
#pragma unroll
    for (int o = 16; o > 0; o >>= 1) ss += __shfl_xor_sync(0xffffffffu, ss, o);
    if (lane == 0) dst[idx] = post / fmaxf(sqrtf(ss), 1e-12f);
}

// ---------------------------------------------------------------------------
// Kernel 2: split-K partials of kv[b][c][d] = sum_m (k[b][m][c]*rk[b][m])*v[b][m][d]
// CTA tile 128(c) x 128(d), BK=32, 2-stage cp.async pipeline.
// Warps 2(c)x4(d), warp tile 64x32.
// ---------------------------------------------------------------------------
__global__ __launch_bounds__(256) void kv_kernel(const float* __restrict__ k,
                                                 const float* __restrict__ v) {
    extern __shared__ float sm[];
    float* As = sm;                    // [2][32*STA]
    float* Bs = sm + 2 * 32 * STA;     // [2][32*STA]
    float* Rk = Bs + 2 * 32 * STA;     // [2][32]

    const int bz = blockIdx.z;       // b*8 + split
    const int b  = bz >> 3;
    const int sp = bz & 7;
    const int c0 = blockIdx.y * 128;
    const int d0 = blockIdx.x * 128;
    const int m_base = sp * (KM_PER_SPLIT * 32);

    const int t = threadIdx.x, lane = t & 31, wid = t >> 5;
    const int g = lane >> 2, tig = lane & 3;
    const int wc = (wid >> 2) * 64;
    const int wd = (wid & 3) * 32;

    const int lr = t >> 3;           // 0..31 (tile row)
    const int lq = (t & 7) * 4;      // word col base, iterate +32

    const float* kb  = k + (size_t)b * M_ * C_ + c0;
    const float* vb  = v + (size_t)b * M_ * C_ + d0;
    const float* rkb = g_rk + b * M_;

    // prologue: stage 0
    {
        const int m0 = m_base;
#pragma unroll
        for (int i = 0; i < 4; i++) {
            cp16(&As[lr * STA + lq + i * 32], kb + (size_t)(m0 + lr) * C_ + lq + i * 32);
            cp16(&Bs[lr * STA + lq + i * 32], vb + (size_t)(m0 + lr) * C_ + lq + i * 32);
        }
        if (t < 8) cp16(&Rk[t * 4], rkb + m0 + t * 4);
        cp_commit();
    }

    float acc[4][4][4] = {};

#pragma unroll 1
    for (int km = 0; km < KM_PER_SPLIT; km++) {
        const int cur = km & 1;
        if (km + 1 < KM_PER_SPLIT) {
            const int nxt = cur ^ 1;
            const int m0 = m_base + (km + 1) * 32;
            float* An = &As[nxt * 32 * STA];
            float* Bn = &Bs[nxt * 32 * STA];
#pragma unroll
            for (int i = 0; i < 4; i++) {
                cp16(&An[lr * STA + lq + i * 32], kb + (size_t)(m0 + lr) * C_ + lq + i * 32);
                cp16(&Bn[lr * STA + lq + i * 32], vb + (size_t)(m0 + lr) * C_ + lq + i * 32);
            }
            if (t < 8) cp16(&Rk[nxt * 32 + t * 4], rkb + m0 + t * 4);
            cp_commit();
            cp_wait<1>();
        } else {
            cp_wait<0>();
        }
        __syncthreads();

        const float* Ac = &As[cur * 32 * STA];
        const float* Bc = &Bs[cur * 32 * STA];
        const float* Rc = &Rk[cur * 32];
#pragma unroll
        for (int kk = 0; kk < 4; kk++) {
            const int k8 = kk * 8;
            const float rk0 = Rc[k8 + tig];
            const float rk1 = Rc[k8 + tig + 4];
            uint32_t af[4][4];
            uint32_t bf[4][2];
#pragma unroll
            for (int mt = 0; mt < 4; mt++) {
                const int row = wc + mt * 16 + g;
                const float* a0 = &Ac[(k8 + tig) * STA + row];
                const float* a1 = &Ac[(k8 + tig + 4) * STA + row];
                af[mt][0] = f2tf(a0[0]);
                af[mt][1] = f2tf(a0[8]);
                af[mt][2] = f2tf(a1[0]);
                af[mt][3] = f2tf(a1[8]);
            }
#pragma unroll
            for (int nt = 0; nt < 4; nt++) {
                const int col = wd + nt * 8 + g;
                bf[nt][0] = f2tf(Bc[(k8 + tig) * STA + col] * rk0);
                bf[nt][1] = f2tf(Bc[(k8 + tig + 4) * STA + col] * rk1);
            }
#pragma unroll
            for (int mt = 0; mt < 4; mt++)
#pragma unroll
                for (int nt = 0; nt < 4; nt++)
                    mma8(acc[mt][nt], af[mt], bf[nt]);
        }
        __syncthreads();
    }

    float* kvp = g_kvp + ((size_t)sp * B_ + b) * C_ * C_;
#pragma unroll
    for (int mt = 0; mt < 4; mt++)
#pragma unroll
        for (int nt = 0; nt < 4; nt++) {
            const int c = c0 + wc + mt * 16 + g;
            const int d = d0 + wd + nt * 8 + tig * 2;
            float2 v0 = make_float2(acc[mt][nt][0], acc[mt][nt][1]);
            float2 v1 = make_float2(acc[mt][nt][2], acc[mt][nt][3]);
            *(float2*)&kvp[(size_t)c * C_ + d]       = v0;
            *(float2*)&kvp[(size_t)(c + 8) * C_ + d] = v1;
        }
}

// ---------------------------------------------------------------------------
// Kernel 2b: reduce the SPLITS partials into g_kv.
// ---------------------------------------------------------------------------
__global__ __launch_bounds__(256) void reduce_kernel() {
    const int i = blockIdx.x * blockDim.x + threadIdx.x;       // float4 index
    const float4* p = (const float4*)g_kvp;
    const int stride = B_ * C_ * C_ / 4;
    float4 a = p[i];
#pragma unroll
    for (int s = 1; s < SPLITS; s++) {
        float4 x = p[s * stride + i];
        a.x += x.x; a.y += x.y; a.z += x.z; a.w += x.w;
    }
    ((float4*)g_kv)[i] = a;
}

// ---------------------------------------------------------------------------
// Kernel 3: out[b][n][d] = rq[b][n] * sum_c q[b][n][c] * kv[b][c][d]
// CTA tile 128(n) x 128(d), BK=32 over c, 2-stage cp.async pipeline.
// rq (with 1/N folded) applied at the epilogue.
// ---------------------------------------------------------------------------
__global__ __launch_bounds__(256) void ctx_kernel(const float* __restrict__ q,
                                                  float* __restrict__ out) {
    extern __shared__ float sm[];
    float* As = sm;                       // [2][128*STQ]  n-major
    float* Bs = sm + 2 * 128 * STQ;       // [2][32*STA]

    const int b  = blockIdx.z;
    const int n0 = blockIdx.y * 128;
    const int d0 = blockIdx.x * 128;

    const int t = threadIdx.x, lane = t & 31, wid = t >> 5;
    const int g = lane >> 2, tig = lane & 3;
    const int wn = (wid >> 2) * 64;
    const int wd = (wid & 3) * 32;

    const int ar = t >> 3;           // base row for A loads (0..31), +32*i
    const int aq = (t & 7) * 4;      // word col (0..28)
    const int br = t >> 3;           // B tile row 0..31
    const int bq = (t & 7) * 4;

    const float* qb  = q + ((size_t)b * N_ + n0) * C_;
    const float* kvb = g_kv + (size_t)b * C_ * C_ + d0;

    // epilogue scales
    float rq0[4], rq1[4];
#pragma unroll
    for (int mt = 0; mt < 4; mt++) {
        const int n = n0 + wn + mt * 16 + g;
        rq0[mt] = __ldg(&g_rq[b * N_ + n]);
        rq1[mt] = __ldg(&g_rq[b * N_ + n + 8]);
    }

    // prologue stage 0 (c-chunk 0)
    {
#pragma unroll
        for (int i = 0; i < 4; i++)
            cp16(&As[(ar + 32 * i) * STQ + aq], qb + (size_t)(ar + 32 * i) * C_ + aq);
#pragma unroll
        for (int i = 0; i < 4; i++)
            cp16(&Bs[br * STA + bq + i * 32], kvb + (size_t)br * C_ + bq + i * 32);
        cp_commit();
    }

    float acc[4][4][4] = {};
    const int KM = C_ / 32;   // 8

#pragma unroll 1
    for (int km = 0; km < KM; km++) {
        const int cur = km & 1;
        if (km + 1 < KM) {
            const int nxt = cur ^ 1;
            const int cb = (km + 1) * 32;
            float* An = &As[nxt * 128 * STQ];
            float* Bn = &Bs[nxt * 32 * STA];
#pragma unroll
            for (int i = 0; i < 4; i++)
                cp16(&An[(ar + 32 * i) * STQ + aq], qb + (size_t)(ar + 32 * i) * C_ + cb + aq);
#pragma unroll
            for (int i = 0; i < 4; i++)
                cp16(&Bn[br * STA + bq + i * 32], kvb + (size_t)(cb + br) * C_ + bq + i * 32);
            cp_commit();
            cp_wait<1>();
        } else {
            cp_wait<0>();
        }
        __syncthreads();

        const float* Ac = &As[cur * 128 * STQ];
        const float* Bc = &Bs[cur * 32 * STA];
#pragma unroll
        for (int kk = 0; kk < 4; kk++) {
            const int k8 = kk * 8;
            uint32_t af[4][4];
            uint32_t bf[4][2];
#pragma unroll
            for (int mt = 0; mt < 4; mt++) {
                const int row = wn + mt * 16 + g;
                af[mt][0] = f2tf(Ac[(size_t)row * STQ + k8 + tig]);
                af[mt][1] = f2tf(Ac[(size_t)(row + 8) * STQ + k8 + tig]);
                af[mt][2] = f2tf(Ac[(size_t)row * STQ + k8 + tig + 4]);
                af[mt][3] = f2tf(Ac[(size_t)(row + 8) * STQ + k8 + tig + 4]);
            }
#pragma unroll
            for (int nt = 0; nt < 4; nt++) {
                const int col = wd + nt * 8 + g;
                bf[nt][0] = f2tf(Bc[(k8 + tig) * STA + col]);
                bf[nt][1] = f2tf(Bc[(k8 + tig + 4) * STA + col]);
            }
#pragma unroll
            for (int mt = 0; mt < 4; mt++)
#pragma unroll
                for (int nt = 0; nt < 4; nt++)
                    mma8(acc[mt][nt], af[mt], bf[nt]);
        }
        __syncthreads();
    }

#pragma unroll
    for (int mt = 0; mt < 4; mt++)
#pragma unroll
        for (int nt = 0; nt < 4; nt++) {
            const int n = n0 + wn + mt * 16 + g;
            const int d = d0 + wd + nt * 8 + tig * 2;
            float2 v0 = make_float2(acc[mt][nt][0] * rq0[mt], acc[mt][nt][1] * rq0[mt]);
            float2 v1 = make_float2(acc[mt][nt][2] * rq1[mt], acc[mt][nt][3] * rq1[mt]);
            *(float2*)&out[((size_t)b * N_ + n) * C_ + d]       = v0;
            *(float2*)&out[((size_t)b * N_ + n + 8) * C_ + d]   = v1;
        }
}

// ---------------------------------------------------------------------------
extern "C" void kernel_launch(void* const* d_in, const int* in_sizes, int n_in,
                              void* d_out, int out_size) {
    const float* q = (const float*)d_in[0];
    const float* k = (const float*)d_in[1];
    const float* v = (const float*)d_in[2];
    float* out = (float*)d_out;

    const int smem_kv  = (2 * 32 * STA + 2 * 32 * STA + 2 * 32) * 4;   // ~70 KB
    const int smem_ctx = (2 * 128 * STQ + 2 * 32 * STA) * 4;           // ~72 KB
    cudaFuncSetAttribute(kv_kernel,  cudaFuncAttributeMaxDynamicSharedMemorySize, smem_kv);
    cudaFuncSetAttribute(ctx_kernel, cudaFuncAttributeMaxDynamicSharedMemorySize, smem_ctx);

    // 1) reciprocal norms
    norm_kernel<<<(B_ * N_ + B_ * M_) / 8, 256>>>(q, k);
    // 2) split-K partial kv
    kv_kernel<<<dim3(1 * (C_ / 128), C_ / 128, B_ * SPLITS), 256, smem_kv>>>(k, v);
    // 2b) reduce partials
    reduce_kernel<<<(B_ * C_ * C_ / 4) / 256, 256>>>();
    // 3) out = q_norm @ kv
    ctx_kernel<<<dim3(C_ / 128, N_ / 128, B_), 256, smem_ctx>>>(q, out);
}